// round 4
// baseline (speedup 1.0000x reference)
#include <cuda_runtime.h>
#include <cuda_bf16.h>
#include <cstddef>

// Problem constants
#define BB 4
#define LL 4096
#define DD 1024
#define HH 8
#define HD 128
#define MM (BB * LL)          // 16384
#define DFF 4096
#define NSPLIT 8              // l-splits for kv accumulation
#define LCHUNK (LL / NSPLIT)  // 512

#define TS 16                 // k-tile depth

// ---------------- scratch (device globals; no allocation allowed) ------------
// Lifetime-aliased arena: qkv (steps 1-3) and ff (steps 6-7) never coexist.
__device__ float g_arena[ (size_t)MM * DFF ];          // 256 MB: qkv | ff
__device__ float g_attn [ (size_t)MM * DD ];           // attention output (b,l,D)
__device__ float g_t1   [ (size_t)MM * DD ];           // attn @ W_out ; later ff@W_ff2
__device__ float g_y1   [ (size_t)MM * DD ];           // rmsnorm1 output
__device__ float g_kv   [ (size_t)BB * HH * HD * HD ]; // 32 x 128 x 128
__device__ float g_ks   [ (size_t)BB * HH * HD ];      // 32 x 128
__device__ float g_kvp  [ (size_t)NSPLIT * BB * HH * HD * HD ]; // partials (16 MB)
__device__ float g_ksp  [ (size_t)NSPLIT * BB * HH * HD ];

__device__ __forceinline__ float elu1f(float x) {
    return x > 0.0f ? x + 1.0f : __expf(x);
}
__device__ __forceinline__ float geluf(float x) {
    return x * normcdff(x);   // exact gelu: x * 0.5*(1+erf(x/sqrt(2)))
}

// ======================= generic fp32 SGEMM (row-major) ======================
// C[M,N] = A[M,K] @ B[K,N].  128x128 block tile, 8x8/thread, double-buffered.
// EPI: 0 = plain store, 1 = gelu
template<int EPI>
__global__ __launch_bounds__(256, 2)
void sgemm_k(const float* __restrict__ A, const float* __restrict__ B,
             float* __restrict__ C, int M, int N, int K)
{
    __shared__ float As[2][TS][132];
    __shared__ float Bs[2][TS][132];

    const int tid = threadIdx.x;
    const int bm = blockIdx.y * 128;
    const int bn = blockIdx.x * 128;
    const int ty = tid >> 4;            // 0..15
    const int tx = tid & 15;            // 0..15
    const int ar = tid >> 2;            // 0..63  (A tile row)
    const int ac = (tid & 3) << 2;      // 0,4,8,12 (A tile col, float4)
    const int br = tid >> 5;            // 0..7   (B tile row)
    const int bc = (tid & 31) << 2;     // 0..124 (B tile col, float4)

    const float* Ap = A + (size_t)(bm + ar) * K + ac;
    const float* Bp = B + (size_t)br * N + bn + bc;

    float4 aR[2], bR[2];
    // stage 0
    aR[0] = *(const float4*)(Ap);
    aR[1] = *(const float4*)(Ap + (size_t)64 * K);
    bR[0] = *(const float4*)(Bp);
    bR[1] = *(const float4*)(Bp + (size_t)8 * N);
#pragma unroll
    for (int i = 0; i < 2; i++) {
        int r = ar + i * 64;
        As[0][ac + 0][r] = (i ? aR[1].x : aR[0].x);
        As[0][ac + 1][r] = (i ? aR[1].y : aR[0].y);
        As[0][ac + 2][r] = (i ? aR[1].z : aR[0].z);
        As[0][ac + 3][r] = (i ? aR[1].w : aR[0].w);
    }
    *(float4*)&Bs[0][br][bc]     = bR[0];
    *(float4*)&Bs[0][br + 8][bc] = bR[1];
    __syncthreads();

    float acc[8][8];
#pragma unroll
    for (int i = 0; i < 8; i++)
#pragma unroll
        for (int j = 0; j < 8; j++) acc[i][j] = 0.0f;

    const int nStages = K / TS;
    for (int s = 0; s < nStages; s++) {
        const int cur = s & 1;
        if (s + 1 < nStages) {
            const float* Ap2 = Ap + (size_t)(s + 1) * TS;
            const float* Bp2 = Bp + (size_t)(s + 1) * TS * N;
            aR[0] = *(const float4*)(Ap2);
            aR[1] = *(const float4*)(Ap2 + (size_t)64 * K);
            bR[0] = *(const float4*)(Bp2);
            bR[1] = *(const float4*)(Bp2 + (size_t)8 * N);
        }
#pragma unroll
        for (int k = 0; k < TS; k++) {
            float4 a0 = *(const float4*)&As[cur][k][ty * 4];
            float4 a1 = *(const float4*)&As[cur][k][64 + ty * 4];
            float4 b0 = *(const float4*)&Bs[cur][k][tx * 4];
            float4 b1 = *(const float4*)&Bs[cur][k][64 + tx * 4];
            float av[8] = {a0.x, a0.y, a0.z, a0.w, a1.x, a1.y, a1.z, a1.w};
            float bv[8] = {b0.x, b0.y, b0.z, b0.w, b1.x, b1.y, b1.z, b1.w};
#pragma unroll
            for (int i = 0; i < 8; i++)
#pragma unroll
                for (int j = 0; j < 8; j++) acc[i][j] += av[i] * bv[j];
        }
        if (s + 1 < nStages) {
            const int nxt = cur ^ 1;
#pragma unroll
            for (int i = 0; i < 2; i++) {
                int r = ar + i * 64;
                As[nxt][ac + 0][r] = (i ? aR[1].x : aR[0].x);
                As[nxt][ac + 1][r] = (i ? aR[1].y : aR[0].y);
                As[nxt][ac + 2][r] = (i ? aR[1].z : aR[0].z);
                As[nxt][ac + 3][r] = (i ? aR[1].w : aR[0].w);
            }
            *(float4*)&Bs[nxt][br][bc]     = bR[0];
            *(float4*)&Bs[nxt][br + 8][bc] = bR[1];
        }
        __syncthreads();
    }

#pragma unroll
    for (int i = 0; i < 8; i++) {
        int row = bm + ((i < 4) ? (ty * 4 + i) : (64 + ty * 4 + i - 4));
#pragma unroll
        for (int jj = 0; jj < 2; jj++) {
            int col = bn + ((jj == 0) ? tx * 4 : 64 + tx * 4);
            float4 v = make_float4(acc[i][jj * 4 + 0], acc[i][jj * 4 + 1],
                                   acc[i][jj * 4 + 2], acc[i][jj * 4 + 3]);
            if (EPI == 1) { v.x = geluf(v.x); v.y = geluf(v.y); v.z = geluf(v.z); v.w = geluf(v.w); }
            *(float4*)&C[(size_t)row * N + col] = v;
        }
    }
}

// =============== linear attention: kv = elu1(k)^T @ v, ksum ================
// grid: (B*H, NSPLIT). Each block: 128(d) x 128(m) partial over LCHUNK tokens.
__global__ __launch_bounds__(256, 2)
void attn_kv_k(const float* __restrict__ qkv, float* __restrict__ kvp,
               float* __restrict__ ksp)
{
    __shared__ float kb[2][TS][132];
    __shared__ float vb[2][TS][132];

    const int tid = threadIdx.x;
    const int bh = blockIdx.x;                 // 0..31
    const int split = blockIdx.y;              // 0..NSPLIT-1
    const int b = bh >> 3, h = bh & 7;
    const int l0 = split * LCHUNK;

    const int ty = tid >> 4, tx = tid & 15;
    const int lr = tid >> 5;                   // 0..7
    const int cc = (tid & 31) << 2;            // 0..124

    const size_t rowstride = 3 * DD;
    const float* kPtr = qkv + (size_t)(b * LL + l0 + lr) * rowstride + DD + h * HD + cc;
    const float* vPtr = qkv + (size_t)(b * LL + l0 + lr) * rowstride + 2 * DD + h * HD + cc;

    float4 kR[2], vR[2];
    auto loadstage = [&](int s) {
        const float* kp = kPtr + (size_t)s * TS * rowstride;
        const float* vp = vPtr + (size_t)s * TS * rowstride;
        kR[0] = *(const float4*)(kp);
        kR[1] = *(const float4*)(kp + (size_t)8 * rowstride);
        vR[0] = *(const float4*)(vp);
        vR[1] = *(const float4*)(vp + (size_t)8 * rowstride);
        kR[0].x = elu1f(kR[0].x); kR[0].y = elu1f(kR[0].y); kR[0].z = elu1f(kR[0].z); kR[0].w = elu1f(kR[0].w);
        kR[1].x = elu1f(kR[1].x); kR[1].y = elu1f(kR[1].y); kR[1].z = elu1f(kR[1].z); kR[1].w = elu1f(kR[1].w);
    };
    auto storestage = [&](int buf) {
        *(float4*)&kb[buf][lr][cc]     = kR[0];
        *(float4*)&kb[buf][lr + 8][cc] = kR[1];
        *(float4*)&vb[buf][lr][cc]     = vR[0];
        *(float4*)&vb[buf][lr + 8][cc] = vR[1];
    };

    loadstage(0);
    storestage(0);
    __syncthreads();

    float acc[8][8];
#pragma unroll
    for (int i = 0; i < 8; i++)
#pragma unroll
        for (int j = 0; j < 8; j++) acc[i][j] = 0.0f;
    float ksAcc = 0.0f;
    const bool lead = (tid < HD);

    const int nStages = LCHUNK / TS;           // 32
    for (int s = 0; s < nStages; s++) {
        const int cur = s & 1;
        if (s + 1 < nStages) loadstage(s + 1);
#pragma unroll
        for (int k = 0; k < TS; k++) {
            float4 a0 = *(const float4*)&kb[cur][k][ty * 4];
            float4 a1 = *(const float4*)&kb[cur][k][64 + ty * 4];
            float4 b0 = *(const float4*)&vb[cur][k][tx * 4];
            float4 b1 = *(const float4*)&vb[cur][k][64 + tx * 4];
            float av[8] = {a0.x, a0.y, a0.z, a0.w, a1.x, a1.y, a1.z, a1.w};
            float bv[8] = {b0.x, b0.y, b0.z, b0.w, b1.x, b1.y, b1.z, b1.w};
#pragma unroll
            for (int i = 0; i < 8; i++)
#pragma unroll
                for (int j = 0; j < 8; j++) acc[i][j] += av[i] * bv[j];
            if (lead) ksAcc += kb[cur][k][tid];
        }
        if (s + 1 < nStages) storestage(cur ^ 1);
        __syncthreads();
    }

    float* kvdst = kvp + ((size_t)split * (BB * HH) + bh) * (HD * HD);
#pragma unroll
    for (int i = 0; i < 8; i++) {
        int d = (i < 4) ? (ty * 4 + i) : (64 + ty * 4 + i - 4);
#pragma unroll
        for (int jj = 0; jj < 2; jj++) {
            int m = (jj == 0) ? tx * 4 : 64 + tx * 4;
            float4 v = make_float4(acc[i][jj * 4 + 0], acc[i][jj * 4 + 1],
                                   acc[i][jj * 4 + 2], acc[i][jj * 4 + 3]);
            *(float4*)&kvdst[(size_t)d * HD + m] = v;
        }
    }
    if (lead) ksp[((size_t)split * (BB * HH) + bh) * HD + tid] = ksAcc;
}

// reduce partials over NSPLIT
__global__ void kv_reduce_k(const float* __restrict__ kvp, const float* __restrict__ ksp,
                            float* __restrict__ kv, float* __restrict__ ks)
{
    const int KVN = BB * HH * HD * HD;     // 524288
    const int KSN = BB * HH * HD;          // 4096
    int i = blockIdx.x * blockDim.x + threadIdx.x;
    if (i < KVN) {
        float s = 0.0f;
#pragma unroll
        for (int p = 0; p < NSPLIT; p++) s += kvp[(size_t)p * KVN + i];
        kv[i] = s;
    } else if (i < KVN + KSN) {
        int j = i - KVN;
        float s = 0.0f;
#pragma unroll
        for (int p = 0; p < NSPLIT; p++) s += ksp[(size_t)p * KSN + j];
        ks[j] = s;
    }
}

// ======= out = (elu1(q) @ kv) / (elu1(q)·ksum + 1e-8), written (b,l,D) ======
// grid: (B*H, L/128)
__global__ __launch_bounds__(256, 2)
void attn_out_k(const float* __restrict__ qkv, const float* __restrict__ kv,
                const float* __restrict__ ks, float* __restrict__ attn)
{
    __shared__ float As[2][TS][132];
    __shared__ float Bs[2][TS][132];
    __shared__ float ksall[HD];

    const int tid = threadIdx.x;
    const int bh = blockIdx.x;
    const int b = bh >> 3, h = bh & 7;
    const int l0 = blockIdx.y * 128;

    const int ty = tid >> 4, tx = tid & 15;
    const int ar = tid >> 2;                // 0..63 (l within tile)
    const int ac = (tid & 3) << 2;          // d within stage
    const int br = tid >> 5;                // 0..7 (d within stage)
    const int bc = (tid & 31) << 2;         // m

    const size_t rowstride = 3 * DD;
    const float* Ap = qkv + (size_t)(b * LL + l0 + ar) * rowstride + h * HD + ac;
    const float* Bp = kv + (size_t)bh * (HD * HD) + (size_t)br * HD + bc;

    if (tid < 32) *(float4*)&ksall[tid * 4] = *(const float4*)&ks[(size_t)bh * HD + tid * 4];

    float4 aR[2], bR[2];
    auto loadstage = [&](int s) {
        const float* ap = Ap + (size_t)s * TS;
        const float* bp = Bp + (size_t)s * TS * HD;
        aR[0] = *(const float4*)(ap);
        aR[1] = *(const float4*)(ap + (size_t)64 * rowstride);
        bR[0] = *(const float4*)(bp);
        bR[1] = *(const float4*)(bp + (size_t)8 * HD);
        aR[0].x = elu1f(aR[0].x); aR[0].y = elu1f(aR[0].y); aR[0].z = elu1f(aR[0].z); aR[0].w = elu1f(aR[0].w);
        aR[1].x = elu1f(aR[1].x); aR[1].y = elu1f(aR[1].y); aR[1].z = elu1f(aR[1].z); aR[1].w = elu1f(aR[1].w);
    };
    auto storestage = [&](int buf) {
#pragma unroll
        for (int i = 0; i < 2; i++) {
            int r = ar + i * 64;
            As[buf][ac + 0][r] = (i ? aR[1].x : aR[0].x);
            As[buf][ac + 1][r] = (i ? aR[1].y : aR[0].y);
            As[buf][ac + 2][r] = (i ? aR[1].z : aR[0].z);
            As[buf][ac + 3][r] = (i ? aR[1].w : aR[0].w);
        }
        *(float4*)&Bs[buf][br][bc]     = bR[0];
        *(float4*)&Bs[buf][br + 8][bc] = bR[1];
    };

    loadstage(0);
    storestage(0);
    __syncthreads();

    float acc[8][8];
#pragma unroll
    for (int i = 0; i < 8; i++)
#pragma unroll
        for (int j = 0; j < 8; j++) acc[i][j] = 0.0f;
    float nrm[8] = {0, 0, 0, 0, 0, 0, 0, 0};

    const int nStages = HD / TS;            // 8
    for (int s = 0; s < nStages; s++) {
        const int cur = s & 1;
        if (s + 1 < nStages) loadstage(s + 1);
#pragma unroll
        for (int k = 0; k < TS; k++) {
            float4 a0 = *(const float4*)&As[cur][k][ty * 4];
            float4 a1 = *(const float4*)&As[cur][k][64 + ty * 4];
            float4 b0 = *(const float4*)&Bs[cur][k][tx * 4];
            float4 b1 = *(const float4*)&Bs[cur][k][64 + tx * 4];
            float av[8] = {a0.x, a0.y, a0.z, a0.w, a1.x, a1.y, a1.z, a1.w};
            float bv[8] = {b0.x, b0.y, b0.z, b0.w, b1.x, b1.y, b1.z, b1.w};
            float kw = ksall[s * TS + k];
#pragma unroll
            for (int i = 0; i < 8; i++) {
                nrm[i] += av[i] * kw;
#pragma unroll
                for (int j = 0; j < 8; j++) acc[i][j] += av[i] * bv[j];
            }
        }
        if (s + 1 < nStages) storestage(cur ^ 1);
        __syncthreads();
    }

#pragma unroll
    for (int i = 0; i < 8; i++) {
        int lrow = (i < 4) ? (ty * 4 + i) : (64 + ty * 4 + i - 4);
        float inv = 1.0f / (nrm[i] + 1e-8f);
        size_t obase = (size_t)(b * LL + l0 + lrow) * DD + h * HD;
#pragma unroll
        for (int jj = 0; jj < 2; jj++) {
            int m = (jj == 0) ? tx * 4 : 64 + tx * 4;
            float4 v = make_float4(acc[i][jj * 4 + 0] * inv, acc[i][jj * 4 + 1] * inv,
                                   acc[i][jj * 4 + 2] * inv, acc[i][jj * 4 + 3] * inv);
            *(float4*)&attn[obase + m] = v;
        }
    }
}

// ================== out = rmsnorm(a + b, g), one block per row ==============
__global__ __launch_bounds__(256)
void rmsnorm_add_k(const float* __restrict__ a, const float* __restrict__ b,
                   const float* __restrict__ g, float* __restrict__ out)
{
    const int row = blockIdx.x;
    const int t = threadIdx.x;
    const float4* ap = (const float4*)(a + (size_t)row * DD);
    const float4* bp = (const float4*)(b + (size_t)row * DD);
    float4 av = ap[t], bv = bp[t];
    float4 v = make_float4(av.x + bv.x, av.y + bv.y, av.z + bv.z, av.w + bv.w);
    float ss = v.x * v.x + v.y * v.y + v.z * v.z + v.w * v.w;
#pragma unroll
    for (int o = 16; o; o >>= 1) ss += __shfl_xor_sync(0xFFFFFFFFu, ss, o);
    __shared__ float ws[8];
    if ((t & 31) == 0) ws[t >> 5] = ss;
    __syncthreads();
    float tot = 0.0f;
#pragma unroll
    for (int w = 0; w < 8; w++) tot += ws[w];
    float scale = rsqrtf(tot * (1.0f / DD) + 1.1920929e-07f);
    float4 gv = ((const float4*)g)[t];
    float4 o4 = make_float4(v.x * scale * gv.x, v.y * scale * gv.y,
                            v.z * scale * gv.z, v.w * scale * gv.w);
    ((float4*)(out + (size_t)row * DD))[t] = o4;
}

// ============================== launcher ====================================
extern "C" void kernel_launch(void* const* d_in, const int* in_sizes, int n_in,
                              void* d_out, int out_size)
{
    const float* x     = (const float*)d_in[0];
    const float* W_qkv = (const float*)d_in[1];
    const float* W_out = (const float*)d_in[2];
    const float* g1    = (const float*)d_in[3];
    const float* W_ff1 = (const float*)d_in[4];
    const float* W_ff2 = (const float*)d_in[5];
    const float* g2    = (const float*)d_in[6];
    float* out = (float*)d_out;

    float *arena, *attn, *t1, *y1, *kvb, *ksb, *kvp, *ksp;
    cudaGetSymbolAddress((void**)&arena, g_arena);
    cudaGetSymbolAddress((void**)&attn,  g_attn);
    cudaGetSymbolAddress((void**)&t1,    g_t1);
    cudaGetSymbolAddress((void**)&y1,    g_y1);
    cudaGetSymbolAddress((void**)&kvb,   g_kv);
    cudaGetSymbolAddress((void**)&ksb,   g_ks);
    cudaGetSymbolAddress((void**)&kvp,   g_kvp);
    cudaGetSymbolAddress((void**)&ksp,   g_ksp);

    float* qkv = arena;   // steps 1-3 (192 MB of the 256 MB arena)
    float* ff  = arena;   // steps 6-7 (256 MB) — lifetimes do not overlap
    float* t2  = t1;      // t1 dead after step 5

    // 1) qkv = x @ W_qkv   [16384,1024] @ [1024,3072]
    sgemm_k<0><<<dim3(3 * DD / 128, MM / 128), 256>>>(x, W_qkv, qkv, MM, 3 * DD, DD);

    // 2) kv partials + reduce
    attn_kv_k<<<dim3(BB * HH, NSPLIT), 256>>>(qkv, kvp, ksp);
    {
        int tot = BB * HH * HD * HD + BB * HH * HD;
        kv_reduce_k<<<(tot + 255) / 256, 256>>>(kvp, ksp, kvb, ksb);
    }

    // 3) attention output
    attn_out_k<<<dim3(BB * HH, LL / 128), 256>>>(qkv, kvb, ksb, attn);

    // 4) t1 = attn @ W_out
    sgemm_k<0><<<dim3(DD / 128, MM / 128), 256>>>(attn, W_out, t1, MM, DD, DD);

    // 5) y1 = rmsnorm(t1 + x, g1)
    rmsnorm_add_k<<<MM, 256>>>(t1, x, g1, y1);

    // 6) ff = gelu(y1 @ W_ff1)   [16384,1024] @ [1024,4096]
    sgemm_k<1><<<dim3(DFF / 128, MM / 128), 256>>>(y1, W_ff1, ff, MM, DFF, DD);

    // 7) t2 = ff @ W_ff2   [16384,4096] @ [4096,1024]
    sgemm_k<0><<<dim3(DD / 128, MM / 128), 256>>>(ff, W_ff2, t2, MM, DD, DFF);

    // 8) out = rmsnorm(t2 + y1, g2)
    rmsnorm_add_k<<<MM, 256>>>(t2, y1, g2, out);
}

// round 11
// speedup vs baseline: 1.0924x; 1.0924x over previous
#include <cuda_runtime.h>
#include <cuda_bf16.h>
#include <cstdint>
#include <cstddef>

// Problem constants
#define BB 4
#define LL 4096
#define DD 1024
#define HH 8
#define HD 128
#define MM (BB * LL)          // 16384
#define DFF 4096
#define NSPLIT 8
#define LCHUNK (LL / NSPLIT)  // 512
#define TS 16

// HMMA GEMM tiling
#define TM 128
#define TN 128
#define KC 32
#define STAGE_BYTES 32768     // 4 subtiles x 128x32 bf16 (8KB)
#define GEMM_SMEM (2 * STAGE_BYTES)

// ---------------- scratch (device globals) ----------------------------------
__device__ __nv_bfloat16 g_big[(size_t)2 * MM * DFF];  // 268MB: qkv fp32 | (ffhi,fflo)
__device__ __nv_bfloat16 g_hl [(size_t)2 * MM * DD];   // 64MB: (xhi,xlo) | (attnhi,attnlo)
__device__ float g_t1 [(size_t)MM * DD];
__device__ float g_y1 [(size_t)MM * DD];
__device__ __nv_bfloat16 g_y1h[(size_t)MM * DD];
__device__ __nv_bfloat16 g_y1l[(size_t)MM * DD];
__device__ __nv_bfloat16 g_wt [(size_t)2 * DFF * DD];  // weight (hi|lo) arena
__device__ float g_kv [(size_t)BB * HH * HD * HD];
__device__ float g_ks [(size_t)BB * HH * HD];
__device__ float g_kvp[(size_t)NSPLIT * BB * HH * HD * HD];
__device__ float g_ksp[(size_t)NSPLIT * BB * HH * HD];

// ---------------- helpers ----------------------------------------------------
__device__ __forceinline__ float elu1f(float x) { return x > 0.0f ? x + 1.0f : __expf(x); }
__device__ __forceinline__ float geluf(float x) { return x * normcdff(x); }

__device__ __forceinline__ void split_bf16(float v, __nv_bfloat16& h, __nv_bfloat16& l) {
    h = __float2bfloat16(v);
    l = __float2bfloat16(v - __bfloat162float(h));
}

__device__ __forceinline__ uint32_t smem_to_u32(const void* p) {
    uint32_t a;
    asm("{ .reg .u64 t; cvta.to.shared.u64 t, %1; cvt.u32.u64 %0, t; }" : "=r"(a) : "l"(p));
    return a;
}

__device__ __forceinline__ void cp16(uint32_t dst, const void* src) {
    asm volatile("cp.async.cg.shared.global [%0], [%1], 16;" :: "r"(dst), "l"(src));
}
#define CP_COMMIT() asm volatile("cp.async.commit_group;" ::: "memory")
#define CP_WAIT1()  asm volatile("cp.async.wait_group 1;" ::: "memory")

__device__ __forceinline__ void ldsm4(uint32_t addr, uint32_t* r) {
    asm volatile("ldmatrix.sync.aligned.m8n8.x4.shared.b16 {%0,%1,%2,%3}, [%4];"
        : "=r"(r[0]), "=r"(r[1]), "=r"(r[2]), "=r"(r[3]) : "r"(addr));
}
__device__ __forceinline__ void mma16816(float* c, const uint32_t* a, const uint32_t* b) {
    asm volatile("mma.sync.aligned.m16n8k16.row.col.f32.bf16.bf16.f32 "
        "{%0,%1,%2,%3}, {%4,%5,%6,%7}, {%8,%9}, {%0,%1,%2,%3};"
        : "+f"(c[0]), "+f"(c[1]), "+f"(c[2]), "+f"(c[3])
        : "r"(a[0]), "r"(a[1]), "r"(a[2]), "r"(a[3]), "r"(b[0]), "r"(b[1]));
}

// swizzled byte offset inside one [128 x 32bf16] subtile: row r, chunk c (8 bf16)
__device__ __forceinline__ uint32_t swz(int r, int c) {
    return (uint32_t)(r * 64 + ((c ^ (r & 3)) << 4));
}

// ==================== HMMA split-bf16 GEMM ===================================
// C[M,N] = (Ahi+Alo)[M,K] @ (Bhi+Blo)[N,K]^T
// EPI 0: fp32 C.   EPI 1: gelu -> split hi/lo bf16 into Chi/Clo.
template<int EPI>
__global__ __launch_bounds__(256, 1)
void tcgemm_k(const __nv_bfloat16* __restrict__ Ahi, const __nv_bfloat16* __restrict__ Alo,
              const __nv_bfloat16* __restrict__ Bhi, const __nv_bfloat16* __restrict__ Blo,
              float* __restrict__ C, __nv_bfloat16* __restrict__ Chi, __nv_bfloat16* __restrict__ Clo,
              int M, int N, int K)
{
    extern __shared__ char smem[];
    const uint32_t sb = smem_to_u32(smem);
    const int tid = threadIdx.x;
    const int lane = tid & 31;
    const int wid = tid >> 5;
    const int mw = wid & 3;           // 0..3 -> 32-row slice
    const int nw = wid >> 2;          // 0..1 -> 64-col slice
    const int m0 = blockIdx.y * TM;
    const int n0 = blockIdx.x * TN;

    const __nv_bfloat16* bases[4] = {Ahi, Alo, Bhi, Blo};

    auto load_stage = [&](int stage, int kk) {
#pragma unroll
        for (int i = 0; i < 8; i++) {
            int u = tid + 256 * i;        // 0..2047
            int sub = u >> 9;             // 0..3
            int idx = u & 511;
            int r = idx >> 2, c = idx & 3;
            int row0 = (sub < 2) ? m0 : n0;
            const __nv_bfloat16* src = bases[sub] + (size_t)(row0 + r) * K + kk + c * 8;
            cp16(sb + stage * STAGE_BYTES + sub * 8192 + swz(r, c), src);
        }
    };

    float acc[2][8][4];
#pragma unroll
    for (int mt = 0; mt < 2; mt++)
#pragma unroll
        for (int nt = 0; nt < 8; nt++)
#pragma unroll
            for (int q = 0; q < 4; q++) acc[mt][nt][q] = 0.0f;

    const int NC = K / KC;
    load_stage(0, 0); CP_COMMIT();
    load_stage(1, KC); CP_COMMIT();

    const int j = lane >> 3, ri = lane & 7;   // ldmatrix lane mapping

    for (int c = 0; c < NC; c++) {
        CP_WAIT1();
        __syncthreads();
        const uint32_t st = sb + (uint32_t)(c & 1) * STAGE_BYTES;

#pragma unroll
        for (int k16 = 0; k16 < 2; k16++) {
            const int chunk = k16 * 2 + (j >> 1);
            uint32_t ahi[2][4], alo[2][4], bhi[8][2], blo[8][2];
#pragma unroll
            for (int mt = 0; mt < 2; mt++) {
                int row = mw * 32 + mt * 16 + ri + (j & 1) * 8;
                uint32_t off = swz(row, chunk);
                ldsm4(st + off, ahi[mt]);          // sub 0
                ldsm4(st + 8192 + off, alo[mt]);   // sub 1
            }
#pragma unroll
            for (int p = 0; p < 4; p++) {
                int row = nw * 64 + p * 16 + ri + (j & 1) * 8;
                uint32_t off = swz(row, chunk);
                uint32_t th[4], tl[4];
                ldsm4(st + 16384 + off, th);       // sub 2
                ldsm4(st + 24576 + off, tl);       // sub 3
                bhi[2 * p][0] = th[0]; bhi[2 * p][1] = th[2];
                bhi[2 * p + 1][0] = th[1]; bhi[2 * p + 1][1] = th[3];
                blo[2 * p][0] = tl[0]; blo[2 * p][1] = tl[2];
                blo[2 * p + 1][0] = tl[1]; blo[2 * p + 1][1] = tl[3];
            }
#pragma unroll
            for (int mt = 0; mt < 2; mt++)
#pragma unroll
                for (int nt = 0; nt < 8; nt++) {
                    mma16816(acc[mt][nt], ahi[mt], bhi[nt]);
                    mma16816(acc[mt][nt], ahi[mt], blo[nt]);
                    mma16816(acc[mt][nt], alo[mt], bhi[nt]);
                }
        }
        __syncthreads();
        if (c + 2 < NC) load_stage(c & 1, (c + 2) * KC);
        CP_COMMIT();
    }

    // epilogue
    const int g = lane >> 2, tc = lane & 3;
#pragma unroll
    for (int mt = 0; mt < 2; mt++) {
        const int r0 = m0 + mw * 32 + mt * 16 + g;
        const int r1 = r0 + 8;
#pragma unroll
        for (int nt = 0; nt < 8; nt++) {
            const int col = n0 + nw * 64 + nt * 8 + 2 * tc;
            if (EPI == 0) {
                *(float2*)&C[(size_t)r0 * N + col] = make_float2(acc[mt][nt][0], acc[mt][nt][1]);
                *(float2*)&C[(size_t)r1 * N + col] = make_float2(acc[mt][nt][2], acc[mt][nt][3]);
            } else {
                float v0 = geluf(acc[mt][nt][0]), v1 = geluf(acc[mt][nt][1]);
                float v2 = geluf(acc[mt][nt][2]), v3 = geluf(acc[mt][nt][3]);
                __nv_bfloat16 h0, l0, h1, l1, h2, l2, h3, l3;
                split_bf16(v0, h0, l0); split_bf16(v1, h1, l1);
                split_bf16(v2, h2, l2); split_bf16(v3, h3, l3);
                __nv_bfloat162 ph0; ph0.x = h0; ph0.y = h1;
                __nv_bfloat162 pl0; pl0.x = l0; pl0.y = l1;
                __nv_bfloat162 ph1; ph1.x = h2; ph1.y = h3;
                __nv_bfloat162 pl1; pl1.x = l2; pl1.y = l3;
                *(__nv_bfloat162*)&Chi[(size_t)r0 * N + col] = ph0;
                *(__nv_bfloat162*)&Clo[(size_t)r0 * N + col] = pl0;
                *(__nv_bfloat162*)&Chi[(size_t)r1 * N + col] = ph1;
                *(__nv_bfloat162*)&Clo[(size_t)r1 * N + col] = pl1;
            }
        }
    }
}

// ==================== elementwise converters =================================
__global__ void cvt_hl_k(const float* __restrict__ in, __nv_bfloat16* __restrict__ hi,
                         __nv_bfloat16* __restrict__ lo, int n)
{
    int i = (blockIdx.x * 256 + threadIdx.x) * 4;
    if (i >= n) return;
    float4 v = *(const float4*)(in + i);
    __nv_bfloat16 h0, l0, h1, l1, h2, l2, h3, l3;
    split_bf16(v.x, h0, l0); split_bf16(v.y, h1, l1);
    split_bf16(v.z, h2, l2); split_bf16(v.w, h3, l3);
    __nv_bfloat162 a, b, c, d;
    a.x = h0; a.y = h1; b.x = h2; b.y = h3;
    c.x = l0; c.y = l1; d.x = l2; d.y = l3;
    *(__nv_bfloat162*)(hi + i) = a; *(__nv_bfloat162*)(hi + i + 2) = b;
    *(__nv_bfloat162*)(lo + i) = c; *(__nv_bfloat162*)(lo + i + 2) = d;
}

// W[K,N] fp32 -> Wt hi/lo [N,K] bf16 (transpose + split)
__global__ void wtr_k(const float* __restrict__ W, __nv_bfloat16* __restrict__ hi,
                      __nv_bfloat16* __restrict__ lo, int K, int N)
{
    __shared__ float t[32][33];
    const int k0 = blockIdx.y * 32, n0 = blockIdx.x * 32;
    const int tx = threadIdx.x, ty = threadIdx.y;
#pragma unroll
    for (int j = 0; j < 4; j++)
        t[ty + 8 * j][tx] = W[(size_t)(k0 + ty + 8 * j) * N + n0 + tx];
    __syncthreads();
#pragma unroll
    for (int j = 0; j < 4; j++) {
        float v = t[tx][ty + 8 * j];
        __nv_bfloat16 h, l;
        split_bf16(v, h, l);
        size_t o = (size_t)(n0 + ty + 8 * j) * K + k0 + tx;
        hi[o] = h; lo[o] = l;
    }
}

// ==================== linear attention (fp32) ================================
__global__ __launch_bounds__(256, 2)
void attn_kv_k(const float* __restrict__ qkv, float* __restrict__ kvp, float* __restrict__ ksp)
{
    __shared__ float kb[2][TS][132];
    __shared__ float vb[2][TS][132];
    const int tid = threadIdx.x;
    const int bh = blockIdx.x, split = blockIdx.y;
    const int b = bh >> 3, h = bh & 7;
    const int l0 = split * LCHUNK;
    const int ty = tid >> 4, tx = tid & 15;
    const int lr = tid >> 5, cc = (tid & 31) << 2;
    const size_t rs = 3 * DD;
    const float* kP = qkv + (size_t)(b * LL + l0 + lr) * rs + DD + h * HD + cc;
    const float* vP = qkv + (size_t)(b * LL + l0 + lr) * rs + 2 * DD + h * HD + cc;

    float4 kR[2], vR[2];
    auto ld = [&](int s) {
        const float* kp = kP + (size_t)s * TS * rs;
        const float* vp = vP + (size_t)s * TS * rs;
        kR[0] = *(const float4*)(kp); kR[1] = *(const float4*)(kp + (size_t)8 * rs);
        vR[0] = *(const float4*)(vp); vR[1] = *(const float4*)(vp + (size_t)8 * rs);
        kR[0].x = elu1f(kR[0].x); kR[0].y = elu1f(kR[0].y); kR[0].z = elu1f(kR[0].z); kR[0].w = elu1f(kR[0].w);
        kR[1].x = elu1f(kR[1].x); kR[1].y = elu1f(kR[1].y); kR[1].z = elu1f(kR[1].z); kR[1].w = elu1f(kR[1].w);
    };
    auto st = [&](int bu) {
        *(float4*)&kb[bu][lr][cc] = kR[0]; *(float4*)&kb[bu][lr + 8][cc] = kR[1];
        *(float4*)&vb[bu][lr][cc] = vR[0]; *(float4*)&vb[bu][lr + 8][cc] = vR[1];
    };
    ld(0); st(0); __syncthreads();

    float acc[8][8];
#pragma unroll
    for (int i = 0; i < 8; i++)
#pragma unroll
        for (int j = 0; j < 8; j++) acc[i][j] = 0.0f;
    float ksA = 0.0f;
    const bool lead = (tid < HD);
    const int nS = LCHUNK / TS;
    for (int s = 0; s < nS; s++) {
        const int cur = s & 1;
        if (s + 1 < nS) ld(s + 1);
#pragma unroll
        for (int k = 0; k < TS; k++) {
            float4 a0 = *(const float4*)&kb[cur][k][ty * 4];
            float4 a1 = *(const float4*)&kb[cur][k][64 + ty * 4];
            float4 b0 = *(const float4*)&vb[cur][k][tx * 4];
            float4 b1 = *(const float4*)&vb[cur][k][64 + tx * 4];
            float av[8] = {a0.x, a0.y, a0.z, a0.w, a1.x, a1.y, a1.z, a1.w};
            float bv[8] = {b0.x, b0.y, b0.z, b0.w, b1.x, b1.y, b1.z, b1.w};
#pragma unroll
            for (int i = 0; i < 8; i++)
#pragma unroll
                for (int j = 0; j < 8; j++) acc[i][j] += av[i] * bv[j];
            if (lead) ksA += kb[cur][k][tid];
        }
        if (s + 1 < nS) st(cur ^ 1);
        __syncthreads();
    }
    float* kvd = kvp + ((size_t)split * (BB * HH) + bh) * (HD * HD);
#pragma unroll
    for (int i = 0; i < 8; i++) {
        int d = (i < 4) ? (ty * 4 + i) : (64 + ty * 4 + i - 4);
#pragma unroll
        for (int jj = 0; jj < 2; jj++) {
            int m = (jj == 0) ? tx * 4 : 64 + tx * 4;
            *(float4*)&kvd[(size_t)d * HD + m] =
                make_float4(acc[i][jj * 4], acc[i][jj * 4 + 1], acc[i][jj * 4 + 2], acc[i][jj * 4 + 3]);
        }
    }
    if (lead) ksp[((size_t)split * (BB * HH) + bh) * HD + tid] = ksA;
}

__global__ void kv_reduce_k(const float* __restrict__ kvp, const float* __restrict__ ksp,
                            float* __restrict__ kv, float* __restrict__ ks)
{
    const int KVN = BB * HH * HD * HD, KSN = BB * HH * HD;
    int i = blockIdx.x * blockDim.x + threadIdx.x;
    if (i < KVN) {
        float s = 0.0f;
#pragma unroll
        for (int p = 0; p < NSPLIT; p++) s += kvp[(size_t)p * KVN + i];
        kv[i] = s;
    } else if (i < KVN + KSN) {
        int j = i - KVN;
        float s = 0.0f;
#pragma unroll
        for (int p = 0; p < NSPLIT; p++) s += ksp[(size_t)p * KSN + j];
        ks[j] = s;
    }
}

// attn out: (elu1(q) @ kv) / (elu1(q).ksum + 1e-8) -> hi/lo bf16 (b,l,D)
__global__ __launch_bounds__(256, 2)
void attn_out_k(const float* __restrict__ qkv, const float* __restrict__ kv,
                const float* __restrict__ ks, __nv_bfloat16* __restrict__ ohi,
                __nv_bfloat16* __restrict__ olo)
{
    __shared__ float As[2][TS][132];
    __shared__ float Bs[2][TS][132];
    __shared__ float ksall[HD];
    const int tid = threadIdx.x;
    const int bh = blockIdx.x;
    const int b = bh >> 3, h = bh & 7;
    const int l0 = blockIdx.y * 128;
    const int ty = tid >> 4, tx = tid & 15;
    const int ar = tid >> 2, ac = (tid & 3) << 2;
    const int br = tid >> 5, bc = (tid & 31) << 2;
    const size_t rs = 3 * DD;
    const float* Ap = qkv + (size_t)(b * LL + l0 + ar) * rs + h * HD + ac;
    const float* Bp = kv + (size_t)bh * (HD * HD) + (size_t)br * HD + bc;
    if (tid < 32) *(float4*)&ksall[tid * 4] = *(const float4*)&ks[(size_t)bh * HD + tid * 4];

    float4 aR[2], bR[2];
    auto ld = [&](int s) {
        const float* ap = Ap + (size_t)s * TS;
        const float* bp = Bp + (size_t)s * TS * HD;
        aR[0] = *(const float4*)(ap); aR[1] = *(const float4*)(ap + (size_t)64 * rs);
        bR[0] = *(const float4*)(bp); bR[1] = *(const float4*)(bp + (size_t)8 * HD);
        aR[0].x = elu1f(aR[0].x); aR[0].y = elu1f(aR[0].y); aR[0].z = elu1f(aR[0].z); aR[0].w = elu1f(aR[0].w);
        aR[1].x = elu1f(aR[1].x); aR[1].y = elu1f(aR[1].y); aR[1].z = elu1f(aR[1].z); aR[1].w = elu1f(aR[1].w);
    };
    auto st = [&](int bu) {
#pragma unroll
        for (int i = 0; i < 2; i++) {
            int r = ar + i * 64;
            As[bu][ac + 0][r] = (i ? aR[1].x : aR[0].x);
            As[bu][ac + 1][r] = (i ? aR[1].y : aR[0].y);
            As[bu][ac + 2][r] = (i ? aR[1].z : aR[0].z);
            As[bu][ac + 3][r] = (i ? aR[1].w : aR[0].w);
        }
        *(float4*)&Bs[bu][br][bc] = bR[0];
        *(float4*)&Bs[bu][br + 8][bc] = bR[1];
    };
    ld(0); st(0); __syncthreads();

    float acc[8][8];
#pragma unroll
    for (int i = 0; i < 8; i++)
#pragma unroll
        for (int j = 0; j < 8; j++) acc[i][j] = 0.0f;
    float nrm[8] = {0, 0, 0, 0, 0, 0, 0, 0};
    const int nS = HD / TS;
    for (int s = 0; s < nS; s++) {
        const int cur = s & 1;
        if (s + 1 < nS) ld(s + 1);
#pragma unroll
        for (int k = 0; k < TS; k++) {
            float4 a0 = *(const float4*)&As[cur][k][ty * 4];
            float4 a1 = *(const float4*)&As[cur][k][64 + ty * 4];
            float4 b0 = *(const float4*)&Bs[cur][k][tx * 4];
            float4 b1 = *(const float4*)&Bs[cur][k][64 + tx * 4];
            float av[8] = {a0.x, a0.y, a0.z, a0.w, a1.x, a1.y, a1.z, a1.w};
            float bv[8] = {b0.x, b0.y, b0.z, b0.w, b1.x, b1.y, b1.z, b1.w};
            float kw = ksall[s * TS + k];
#pragma unroll
            for (int i = 0; i < 8; i++) {
                nrm[i] += av[i] * kw;
#pragma unroll
                for (int j = 0; j < 8; j++) acc[i][j] += av[i] * bv[j];
            }
        }
        if (s + 1 < nS) st(cur ^ 1);
        __syncthreads();
    }
#pragma unroll
    for (int i = 0; i < 8; i++) {
        int lrow = (i < 4) ? (ty * 4 + i) : (64 + ty * 4 + i - 4);
        float inv = 1.0f / (nrm[i] + 1e-8f);
        size_t ob = (size_t)(b * LL + l0 + lrow) * DD + h * HD;
#pragma unroll
        for (int jj = 0; jj < 2; jj++) {
            int m = (jj == 0) ? tx * 4 : 64 + tx * 4;
            __nv_bfloat16 h0, l0v, h1, l1, h2, l2, h3, l3;
            split_bf16(acc[i][jj * 4 + 0] * inv, h0, l0v);
            split_bf16(acc[i][jj * 4 + 1] * inv, h1, l1);
            split_bf16(acc[i][jj * 4 + 2] * inv, h2, l2);
            split_bf16(acc[i][jj * 4 + 3] * inv, h3, l3);
            __nv_bfloat162 p0, p1, q0, q1;
            p0.x = h0; p0.y = h1; p1.x = h2; p1.y = h3;
            q0.x = l0v; q0.y = l1; q1.x = l2; q1.y = l3;
            *(__nv_bfloat162*)(ohi + ob + m) = p0; *(__nv_bfloat162*)(ohi + ob + m + 2) = p1;
            *(__nv_bfloat162*)(olo + ob + m) = q0; *(__nv_bfloat162*)(olo + ob + m + 2) = q1;
        }
    }
}

// ==================== rmsnorm ================================================
template<int EMIT_HL>
__global__ __launch_bounds__(256)
void rmsnorm_k(const float* __restrict__ a, const float* __restrict__ b,
               const float* __restrict__ g, float* __restrict__ out,
               __nv_bfloat16* __restrict__ ohi, __nv_bfloat16* __restrict__ olo)
{
    const int row = blockIdx.x;
    const int t = threadIdx.x;
    float4 av = ((const float4*)(a + (size_t)row * DD))[t];
    float4 bv = ((const float4*)(b + (size_t)row * DD))[t];
    float4 v = make_float4(av.x + bv.x, av.y + bv.y, av.z + bv.z, av.w + bv.w);
    float ss = v.x * v.x + v.y * v.y + v.z * v.z + v.w * v.w;
#pragma unroll
    for (int o = 16; o; o >>= 1) ss += __shfl_xor_sync(0xFFFFFFFFu, ss, o);
    __shared__ float ws[8];
    if ((t & 31) == 0) ws[t >> 5] = ss;
    __syncthreads();
    float tot = 0.0f;
#pragma unroll
    for (int w = 0; w < 8; w++) tot += ws[w];
    float sc = rsqrtf(tot * (1.0f / DD) + 1.1920929e-07f);
    float4 gv = ((const float4*)g)[t];
    float4 o4 = make_float4(v.x * sc * gv.x, v.y * sc * gv.y, v.z * sc * gv.z, v.w * sc * gv.w);
    ((float4*)(out + (size_t)row * DD))[t] = o4;
    if (EMIT_HL) {
        __nv_bfloat16 h0, l0, h1, l1, h2, l2, h3, l3;
        split_bf16(o4.x, h0, l0); split_bf16(o4.y, h1, l1);
        split_bf16(o4.z, h2, l2); split_bf16(o4.w, h3, l3);
        __nv_bfloat162 p0, p1, q0, q1;
        p0.x = h0; p0.y = h1; p1.x = h2; p1.y = h3;
        q0.x = l0; q0.y = l1; q1.x = l2; q1.y = l3;
        size_t ob = (size_t)row * DD + t * 4;
        *(__nv_bfloat162*)(ohi + ob) = p0; *(__nv_bfloat162*)(ohi + ob + 2) = p1;
        *(__nv_bfloat162*)(olo + ob) = q0; *(__nv_bfloat162*)(olo + ob + 2) = q1;
    }
}

// ============================== launcher =====================================
extern "C" void kernel_launch(void* const* d_in, const int* in_sizes, int n_in,
                              void* d_out, int out_size)
{
    const float* x     = (const float*)d_in[0];
    const float* W_qkv = (const float*)d_in[1];
    const float* W_out = (const float*)d_in[2];
    const float* g1    = (const float*)d_in[3];
    const float* W_ff1 = (const float*)d_in[4];
    const float* W_ff2 = (const float*)d_in[5];
    const float* g2    = (const float*)d_in[6];
    float* out = (float*)d_out;

    __nv_bfloat16 *big, *hl, *y1h, *y1l, *wt;
    float *t1, *y1, *kvb, *ksb, *kvp, *ksp;
    cudaGetSymbolAddress((void**)&big, g_big);
    cudaGetSymbolAddress((void**)&hl,  g_hl);
    cudaGetSymbolAddress((void**)&t1,  g_t1);
    cudaGetSymbolAddress((void**)&y1,  g_y1);
    cudaGetSymbolAddress((void**)&y1h, g_y1h);
    cudaGetSymbolAddress((void**)&y1l, g_y1l);
    cudaGetSymbolAddress((void**)&wt,  g_wt);
    cudaGetSymbolAddress((void**)&kvb, g_kv);
    cudaGetSymbolAddress((void**)&ksb, g_ks);
    cudaGetSymbolAddress((void**)&kvp, g_kvp);
    cudaGetSymbolAddress((void**)&ksp, g_ksp);

    cudaFuncSetAttribute(tcgemm_k<0>, cudaFuncAttributeMaxDynamicSharedMemorySize, GEMM_SMEM);
    cudaFuncSetAttribute(tcgemm_k<1>, cudaFuncAttributeMaxDynamicSharedMemorySize, GEMM_SMEM);

    __nv_bfloat16* xhi = hl;
    __nv_bfloat16* xlo = hl + (size_t)MM * DD;
    __nv_bfloat16* athi = hl;                       // alias: x hl dead after GEMM1
    __nv_bfloat16* atlo = hl + (size_t)MM * DD;
    float* qkvf = (float*)big;                      // 192MB of 268MB arena
    __nv_bfloat16* ffhi = big;                      // alias: qkv dead after attn_out
    __nv_bfloat16* fflo = big + (size_t)MM * DFF;
    __nv_bfloat16* whi = wt;
    __nv_bfloat16* wlo = wt + (size_t)DFF * DD;
    float* t2 = t1;                                 // t1 dead after rmsnorm1

    // 1) x -> hi/lo
    cvt_hl_k<<<MM * DD / 1024, 256>>>(x, xhi, xlo, MM * DD);
    // 2) W_qkv^T hi/lo ; qkv = x @ W_qkv  (fp32 out)
    wtr_k<<<dim3(3 * DD / 32, DD / 32), dim3(32, 8)>>>(W_qkv, whi, wlo, DD, 3 * DD);
    tcgemm_k<0><<<dim3(3 * DD / TN, MM / TM), 256, GEMM_SMEM>>>(
        xhi, xlo, whi, wlo, qkvf, nullptr, nullptr, MM, 3 * DD, DD);
    // 3) linear attention (fp32) -> attn hi/lo
    attn_kv_k<<<dim3(BB * HH, NSPLIT), 256>>>(qkvf, kvp, ksp);
    {
        int tot = BB * HH * HD * HD + BB * HH * HD;
        kv_reduce_k<<<(tot + 255) / 256, 256>>>(kvp, ksp, kvb, ksb);
    }
    attn_out_k<<<dim3(BB * HH, LL / 128), 256>>>(qkvf, kvb, ksb, athi, atlo);
    // 4) t1 = attn @ W_out
    wtr_k<<<dim3(DD / 32, DD / 32), dim3(32, 8)>>>(W_out, whi, wlo, DD, DD);
    tcgemm_k<0><<<dim3(DD / TN, MM / TM), 256, GEMM_SMEM>>>(
        athi, atlo, whi, wlo, t1, nullptr, nullptr, MM, DD, DD);
    // 5) y1 = rmsnorm(t1 + x) (+ hi/lo)
    rmsnorm_k<1><<<MM, 256>>>(t1, x, g1, y1, y1h, y1l);
    // 6) ff = gelu(y1 @ W_ff1) -> hi/lo directly
    wtr_k<<<dim3(DFF / 32, DD / 32), dim3(32, 8)>>>(W_ff1, whi, wlo, DD, DFF);
    tcgemm_k<1><<<dim3(DFF / TN, MM / TM), 256, GEMM_SMEM>>>(
        y1h, y1l, whi, wlo, nullptr, ffhi, fflo, MM, DFF, DD);
    // 7) t2 = ff @ W_ff2
    wtr_k<<<dim3(DD / 32, DFF / 32), dim3(32, 8)>>>(W_ff2, whi, wlo, DFF, DD);
    tcgemm_k<0><<<dim3(DD / TN, MM / TM), 256, GEMM_SMEM>>>(
        ffhi, fflo, whi, wlo, t2, nullptr, nullptr, MM, DD, DFF);
    // 8) out = rmsnorm(t2 + y1)
    rmsnorm_k<0><<<MM, 256>>>(t2, y1, g2, out, nullptr, nullptr);
}

// round 14
// speedup vs baseline: 2.0809x; 1.9049x over previous
#include <cuda_runtime.h>
#include <cuda_bf16.h>
#include <cstdint>
#include <cstddef>

// Problem constants
#define BB 4
#define LL 4096
#define DD 1024
#define HH 8
#define HD 128
#define MM (BB * LL)          // 16384
#define DFF 4096
#define NSPLIT 8
#define LCHUNK (LL / NSPLIT)  // 512
#define TS 16

// HMMA GEMM tiling
#define TM 128
#define TN 128
#define KC 32
#define STAGE_BYTES 32768     // 4 subtiles x 128x32 bf16 (8KB)
#define GEMM_SMEM (2 * STAGE_BYTES)

// ---------------- scratch (device globals) ----------------------------------
__device__ __nv_bfloat16 g_big[(size_t)2 * MM * DFF];  // 268MB: qkv fp32 | (ffhi,fflo)
__device__ __nv_bfloat16 g_hl [(size_t)2 * MM * DD];   // 64MB: (xhi,xlo) | (attnhi,attnlo)
__device__ float g_t1 [(size_t)MM * DD];
__device__ float g_y1 [(size_t)MM * DD];
__device__ __nv_bfloat16 g_y1h[(size_t)MM * DD];
__device__ __nv_bfloat16 g_y1l[(size_t)MM * DD];
__device__ __nv_bfloat16 g_wt [(size_t)2 * DFF * DD];  // weight (hi|lo) arena
__device__ float g_kv [(size_t)BB * HH * HD * HD];
__device__ float g_ks [(size_t)BB * HH * HD];
__device__ float g_kvp[(size_t)NSPLIT * BB * HH * HD * HD];
__device__ float g_ksp[(size_t)NSPLIT * BB * HH * HD];

// ---------------- helpers ----------------------------------------------------
__device__ __forceinline__ float elu1f(float x) { return x > 0.0f ? x + 1.0f : __expf(x); }
__device__ __forceinline__ float geluf(float x) { return x * normcdff(x); }

__device__ __forceinline__ void split_bf16(float v, __nv_bfloat16& h, __nv_bfloat16& l) {
    h = __float2bfloat16(v);
    l = __float2bfloat16(v - __bfloat162float(h));
}

__device__ __forceinline__ uint32_t smem_to_u32(const void* p) {
    uint32_t a;
    asm("{ .reg .u64 t; cvta.to.shared.u64 t, %1; cvt.u32.u64 %0, t; }" : "=r"(a) : "l"(p));
    return a;
}

__device__ __forceinline__ void cp16(uint32_t dst, const void* src) {
    asm volatile("cp.async.cg.shared.global [%0], [%1], 16;" :: "r"(dst), "l"(src));
}
#define CP_COMMIT() asm volatile("cp.async.commit_group;" ::: "memory")
#define CP_WAIT1()  asm volatile("cp.async.wait_group 1;" ::: "memory")

__device__ __forceinline__ void ldsm4(uint32_t addr, uint32_t* r) {
    asm volatile("ldmatrix.sync.aligned.m8n8.x4.shared.b16 {%0,%1,%2,%3}, [%4];"
        : "=r"(r[0]), "=r"(r[1]), "=r"(r[2]), "=r"(r[3]) : "r"(addr));
}
__device__ __forceinline__ void mma16816(float* c, const uint32_t* a, const uint32_t* b) {
    asm volatile("mma.sync.aligned.m16n8k16.row.col.f32.bf16.bf16.f32 "
        "{%0,%1,%2,%3}, {%4,%5,%6,%7}, {%8,%9}, {%0,%1,%2,%3};"
        : "+f"(c[0]), "+f"(c[1]), "+f"(c[2]), "+f"(c[3])
        : "r"(a[0]), "r"(a[1]), "r"(a[2]), "r"(a[3]), "r"(b[0]), "r"(b[1]));
}

// swizzled byte offset inside one [128 x 32bf16] subtile: row r, chunk c (8 bf16)
__device__ __forceinline__ uint32_t swz(int r, int c) {
    return (uint32_t)(r * 64 + ((c ^ (r & 3)) << 4));
}

// ==================== HMMA split-bf16 GEMM ===================================
// C[M,N] = (Ahi+Alo)[M,K] @ (Bhi+Blo)[N,K]^T
// EPI 0: fp32 C.   EPI 1: gelu -> split hi/lo bf16 into Chi/Clo.
// 2 CTAs/SM (<=128 regs): B fragments loaded/consumed per-p to cap live state.
template<int EPI>
__global__ __launch_bounds__(256, 2)
void tcgemm_k(const __nv_bfloat16* __restrict__ Ahi, const __nv_bfloat16* __restrict__ Alo,
              const __nv_bfloat16* __restrict__ Bhi, const __nv_bfloat16* __restrict__ Blo,
              float* __restrict__ C, __nv_bfloat16* __restrict__ Chi, __nv_bfloat16* __restrict__ Clo,
              int M, int N, int K)
{
    extern __shared__ char smem[];
    const uint32_t sb = smem_to_u32(smem);
    const int tid = threadIdx.x;
    const int lane = tid & 31;
    const int wid = tid >> 5;
    const int mw = wid & 3;           // 0..3 -> 32-row slice
    const int nw = wid >> 2;          // 0..1 -> 64-col slice
    const int m0 = blockIdx.y * TM;
    const int n0 = blockIdx.x * TN;

    const __nv_bfloat16* bases[4] = {Ahi, Alo, Bhi, Blo};

    auto load_stage = [&](int stage, int kk) {
#pragma unroll
        for (int i = 0; i < 8; i++) {
            int u = tid + 256 * i;        // 0..2047
            int sub = u >> 9;             // 0..3
            int idx = u & 511;
            int r = idx >> 2, c = idx & 3;
            int row0 = (sub < 2) ? m0 : n0;
            const __nv_bfloat16* src = bases[sub] + (size_t)(row0 + r) * K + kk + c * 8;
            cp16(sb + stage * STAGE_BYTES + sub * 8192 + swz(r, c), src);
        }
    };

    float acc[2][8][4];
#pragma unroll
    for (int mt = 0; mt < 2; mt++)
#pragma unroll
        for (int nt = 0; nt < 8; nt++)
#pragma unroll
            for (int q = 0; q < 4; q++) acc[mt][nt][q] = 0.0f;

    const int NC = K / KC;
    load_stage(0, 0); CP_COMMIT();
    load_stage(1, KC); CP_COMMIT();

    const int j = lane >> 3, ri = lane & 7;   // ldmatrix lane mapping

    for (int c = 0; c < NC; c++) {
        CP_WAIT1();
        __syncthreads();
        const uint32_t st = sb + (uint32_t)(c & 1) * STAGE_BYTES;

#pragma unroll
        for (int k16 = 0; k16 < 2; k16++) {
            const int chunk = k16 * 2 + (j >> 1);
            uint32_t ahi[2][4], alo[2][4];
#pragma unroll
            for (int mt = 0; mt < 2; mt++) {
                int row = mw * 32 + mt * 16 + ri + (j & 1) * 8;
                uint32_t off = swz(row, chunk);
                ldsm4(st + off, ahi[mt]);          // sub 0
                ldsm4(st + 8192 + off, alo[mt]);   // sub 1
            }
#pragma unroll
            for (int p = 0; p < 4; p++) {
                int row = nw * 64 + p * 16 + ri + (j & 1) * 8;
                uint32_t off = swz(row, chunk);
                uint32_t th[4], tl[4];
                ldsm4(st + 16384 + off, th);       // sub 2
                ldsm4(st + 24576 + off, tl);       // sub 3
                uint32_t bh0[2] = {th[0], th[2]};
                uint32_t bh1[2] = {th[1], th[3]};
                uint32_t bl0[2] = {tl[0], tl[2]};
                uint32_t bl1[2] = {tl[1], tl[3]};
#pragma unroll
                for (int mt = 0; mt < 2; mt++) {
                    mma16816(acc[mt][2 * p],     ahi[mt], bh0);
                    mma16816(acc[mt][2 * p],     ahi[mt], bl0);
                    mma16816(acc[mt][2 * p],     alo[mt], bh0);
                    mma16816(acc[mt][2 * p + 1], ahi[mt], bh1);
                    mma16816(acc[mt][2 * p + 1], ahi[mt], bl1);
                    mma16816(acc[mt][2 * p + 1], alo[mt], bh1);
                }
            }
        }
        __syncthreads();
        if (c + 2 < NC) load_stage(c & 1, (c + 2) * KC);
        CP_COMMIT();
    }

    // epilogue
    const int g = lane >> 2, tc = lane & 3;
#pragma unroll
    for (int mt = 0; mt < 2; mt++) {
        const int r0 = m0 + mw * 32 + mt * 16 + g;
        const int r1 = r0 + 8;
#pragma unroll
        for (int nt = 0; nt < 8; nt++) {
            const int col = n0 + nw * 64 + nt * 8 + 2 * tc;
            if (EPI == 0) {
                *(float2*)&C[(size_t)r0 * N + col] = make_float2(acc[mt][nt][0], acc[mt][nt][1]);
                *(float2*)&C[(size_t)r1 * N + col] = make_float2(acc[mt][nt][2], acc[mt][nt][3]);
            } else {
                float v0 = geluf(acc[mt][nt][0]), v1 = geluf(acc[mt][nt][1]);
                float v2 = geluf(acc[mt][nt][2]), v3 = geluf(acc[mt][nt][3]);
                __nv_bfloat16 h0, l0, h1, l1, h2, l2, h3, l3;
                split_bf16(v0, h0, l0); split_bf16(v1, h1, l1);
                split_bf16(v2, h2, l2); split_bf16(v3, h3, l3);
                __nv_bfloat162 ph0; ph0.x = h0; ph0.y = h1;
                __nv_bfloat162 pl0; pl0.x = l0; pl0.y = l1;
                __nv_bfloat162 ph1; ph1.x = h2; ph1.y = h3;
                __nv_bfloat162 pl1; pl1.x = l2; pl1.y = l3;
                *(__nv_bfloat162*)&Chi[(size_t)r0 * N + col] = ph0;
                *(__nv_bfloat162*)&Clo[(size_t)r0 * N + col] = pl0;
                *(__nv_bfloat162*)&Chi[(size_t)r1 * N + col] = ph1;
                *(__nv_bfloat162*)&Clo[(size_t)r1 * N + col] = pl1;
            }
        }
    }
}

// ==================== elementwise converters =================================
__global__ void cvt_hl_k(const float* __restrict__ in, __nv_bfloat16* __restrict__ hi,
                         __nv_bfloat16* __restrict__ lo, int n)
{
    int i = (blockIdx.x * 256 + threadIdx.x) * 4;
    if (i >= n) return;
    float4 v = *(const float4*)(in + i);
    __nv_bfloat16 h0, l0, h1, l1, h2, l2, h3, l3;
    split_bf16(v.x, h0, l0); split_bf16(v.y, h1, l1);
    split_bf16(v.z, h2, l2); split_bf16(v.w, h3, l3);
    __nv_bfloat162 a, b, c, d;
    a.x = h0; a.y = h1; b.x = h2; b.y = h3;
    c.x = l0; c.y = l1; d.x = l2; d.y = l3;
    *(__nv_bfloat162*)(hi + i) = a; *(__nv_bfloat162*)(hi + i + 2) = b;
    *(__nv_bfloat162*)(lo + i) = c; *(__nv_bfloat162*)(lo + i + 2) = d;
}

// W[K,N] fp32 -> Wt hi/lo [N,K] bf16 (transpose + split)
__global__ void wtr_k(const float* __restrict__ W, __nv_bfloat16* __restrict__ hi,
                      __nv_bfloat16* __restrict__ lo, int K, int N)
{
    __shared__ float t[32][33];
    const int k0 = blockIdx.y * 32, n0 = blockIdx.x * 32;
    const int tx = threadIdx.x, ty = threadIdx.y;
#pragma unroll
    for (int j = 0; j < 4; j++)
        t[ty + 8 * j][tx] = W[(size_t)(k0 + ty + 8 * j) * N + n0 + tx];
    __syncthreads();
#pragma unroll
    for (int j = 0; j < 4; j++) {
        float v = t[tx][ty + 8 * j];
        __nv_bfloat16 h, l;
        split_bf16(v, h, l);
        size_t o = (size_t)(n0 + ty + 8 * j) * K + k0 + tx;
        hi[o] = h; lo[o] = l;
    }
}

// ==================== linear attention (fp32) ================================
__global__ __launch_bounds__(256, 2)
void attn_kv_k(const float* __restrict__ qkv, float* __restrict__ kvp, float* __restrict__ ksp)
{
    __shared__ float kb[2][TS][132];
    __shared__ float vb[2][TS][132];
    const int tid = threadIdx.x;
    const int bh = blockIdx.x, split = blockIdx.y;
    const int b = bh >> 3, h = bh & 7;
    const int l0 = split * LCHUNK;
    const int ty = tid >> 4, tx = tid & 15;
    const int lr = tid >> 5, cc = (tid & 31) << 2;
    const size_t rs = 3 * DD;
    const float* kP = qkv + (size_t)(b * LL + l0 + lr) * rs + DD + h * HD + cc;
    const float* vP = qkv + (size_t)(b * LL + l0 + lr) * rs + 2 * DD + h * HD + cc;

    float4 kR[2], vR[2];
    auto ld = [&](int s) {
        const float* kp = kP + (size_t)s * TS * rs;
        const float* vp = vP + (size_t)s * TS * rs;
        kR[0] = *(const float4*)(kp); kR[1] = *(const float4*)(kp + (size_t)8 * rs);
        vR[0] = *(const float4*)(vp); vR[1] = *(const float4*)(vp + (size_t)8 * rs);
        kR[0].x = elu1f(kR[0].x); kR[0].y = elu1f(kR[0].y); kR[0].z = elu1f(kR[0].z); kR[0].w = elu1f(kR[0].w);
        kR[1].x = elu1f(kR[1].x); kR[1].y = elu1f(kR[1].y); kR[1].z = elu1f(kR[1].z); kR[1].w = elu1f(kR[1].w);
    };
    auto st = [&](int bu) {
        *(float4*)&kb[bu][lr][cc] = kR[0]; *(float4*)&kb[bu][lr + 8][cc] = kR[1];
        *(float4*)&vb[bu][lr][cc] = vR[0]; *(float4*)&vb[bu][lr + 8][cc] = vR[1];
    };
    ld(0); st(0); __syncthreads();

    float acc[8][8];
#pragma unroll
    for (int i = 0; i < 8; i++)
#pragma unroll
        for (int j = 0; j < 8; j++) acc[i][j] = 0.0f;
    float ksA = 0.0f;
    const bool lead = (tid < HD);
    const int nS = LCHUNK / TS;
    for (int s = 0; s < nS; s++) {
        const int cur = s & 1;
        if (s + 1 < nS) ld(s + 1);
#pragma unroll
        for (int k = 0; k < TS; k++) {
            float4 a0 = *(const float4*)&kb[cur][k][ty * 4];
            float4 a1 = *(const float4*)&kb[cur][k][64 + ty * 4];
            float4 b0 = *(const float4*)&vb[cur][k][tx * 4];
            float4 b1 = *(const float4*)&vb[cur][k][64 + tx * 4];
            float av[8] = {a0.x, a0.y, a0.z, a0.w, a1.x, a1.y, a1.z, a1.w};
            float bv[8] = {b0.x, b0.y, b0.z, b0.w, b1.x, b1.y, b1.z, b1.w};
#pragma unroll
            for (int i = 0; i < 8; i++)
#pragma unroll
                for (int j = 0; j < 8; j++) acc[i][j] += av[i] * bv[j];
            if (lead) ksA += kb[cur][k][tid];
        }
        if (s + 1 < nS) st(cur ^ 1);
        __syncthreads();
    }
    float* kvd = kvp + ((size_t)split * (BB * HH) + bh) * (HD * HD);
#pragma unroll
    for (int i = 0; i < 8; i++) {
        int d = (i < 4) ? (ty * 4 + i) : (64 + ty * 4 + i - 4);
#pragma unroll
        for (int jj = 0; jj < 2; jj++) {
            int m = (jj == 0) ? tx * 4 : 64 + tx * 4;
            *(float4*)&kvd[(size_t)d * HD + m] =
                make_float4(acc[i][jj * 4], acc[i][jj * 4 + 1], acc[i][jj * 4 + 2], acc[i][jj * 4 + 3]);
        }
    }
    if (lead) ksp[((size_t)split * (BB * HH) + bh) * HD + tid] = ksA;
}

__global__ void kv_reduce_k(const float* __restrict__ kvp, const float* __restrict__ ksp,
                            float* __restrict__ kv, float* __restrict__ ks)
{
    const int KVN = BB * HH * HD * HD, KSN = BB * HH * HD;
    int i = blockIdx.x * blockDim.x + threadIdx.x;
    if (i < KVN) {
        float s = 0.0f;
#pragma unroll
        for (int p = 0; p < NSPLIT; p++) s += kvp[(size_t)p * KVN + i];
        kv[i] = s;
    } else if (i < KVN + KSN) {
        int j = i - KVN;
        float s = 0.0f;
#pragma unroll
        for (int p = 0; p < NSPLIT; p++) s += ksp[(size_t)p * KSN + j];
        ks[j] = s;
    }
}

// attn out: (elu1(q) @ kv) / (elu1(q).ksum + 1e-8) -> hi/lo bf16 (b,l,D)
__global__ __launch_bounds__(256, 2)
void attn_out_k(const float* __restrict__ qkv, const float* __restrict__ kv,
                const float* __restrict__ ks, __nv_bfloat16* __restrict__ ohi,
                __nv_bfloat16* __restrict__ olo)
{
    __shared__ float As[2][TS][132];
    __shared__ float Bs[2][TS][132];
    __shared__ float ksall[HD];
    const int tid = threadIdx.x;
    const int bh = blockIdx.x;
    const int b = bh >> 3, h = bh & 7;
    const int l0 = blockIdx.y * 128;
    const int ty = tid >> 4, tx = tid & 15;
    const int ar = tid >> 2, ac = (tid & 3) << 2;
    const int br = tid >> 5, bc = (tid & 31) << 2;
    const size_t rs = 3 * DD;
    const float* Ap = qkv + (size_t)(b * LL + l0 + ar) * rs + h * HD + ac;
    const float* Bp = kv + (size_t)bh * (HD * HD) + (size_t)br * HD + bc;
    if (tid < 32) *(float4*)&ksall[tid * 4] = *(const float4*)&ks[(size_t)bh * HD + tid * 4];

    float4 aR[2], bR[2];
    auto ld = [&](int s) {
        const float* ap = Ap + (size_t)s * TS;
        const float* bp = Bp + (size_t)s * TS * HD;
        aR[0] = *(const float4*)(ap); aR[1] = *(const float4*)(ap + (size_t)64 * rs);
        bR[0] = *(const float4*)(bp); bR[1] = *(const float4*)(bp + (size_t)8 * HD);
        aR[0].x = elu1f(aR[0].x); aR[0].y = elu1f(aR[0].y); aR[0].z = elu1f(aR[0].z); aR[0].w = elu1f(aR[0].w);
        aR[1].x = elu1f(aR[1].x); aR[1].y = elu1f(aR[1].y); aR[1].z = elu1f(aR[1].z); aR[1].w = elu1f(aR[1].w);
    };
    auto st = [&](int bu) {
#pragma unroll
        for (int i = 0; i < 2; i++) {
            int r = ar + i * 64;
            As[bu][ac + 0][r] = (i ? aR[1].x : aR[0].x);
            As[bu][ac + 1][r] = (i ? aR[1].y : aR[0].y);
            As[bu][ac + 2][r] = (i ? aR[1].z : aR[0].z);
            As[bu][ac + 3][r] = (i ? aR[1].w : aR[0].w);
        }
        *(float4*)&Bs[bu][br][bc] = bR[0];
        *(float4*)&Bs[bu][br + 8][bc] = bR[1];
    };
    ld(0); st(0); __syncthreads();

    float acc[8][8];
#pragma unroll
    for (int i = 0; i < 8; i++)
#pragma unroll
        for (int j = 0; j < 8; j++) acc[i][j] = 0.0f;
    float nrm[8] = {0, 0, 0, 0, 0, 0, 0, 0};
    const int nS = HD / TS;
    for (int s = 0; s < nS; s++) {
        const int cur = s & 1;
        if (s + 1 < nS) ld(s + 1);
#pragma unroll
        for (int k = 0; k < TS; k++) {
            float4 a0 = *(const float4*)&As[cur][k][ty * 4];
            float4 a1 = *(const float4*)&As[cur][k][64 + ty * 4];
            float4 b0 = *(const float4*)&Bs[cur][k][tx * 4];
            float4 b1 = *(const float4*)&Bs[cur][k][64 + tx * 4];
            float av[8] = {a0.x, a0.y, a0.z, a0.w, a1.x, a1.y, a1.z, a1.w};
            float bv[8] = {b0.x, b0.y, b0.z, b0.w, b1.x, b1.y, b1.z, b1.w};
            float kw = ksall[s * TS + k];
#pragma unroll
            for (int i = 0; i < 8; i++) {
                nrm[i] += av[i] * kw;
#pragma unroll
                for (int j = 0; j < 8; j++) acc[i][j] += av[i] * bv[j];
            }
        }
        if (s + 1 < nS) st(cur ^ 1);
        __syncthreads();
    }
#pragma unroll
    for (int i = 0; i < 8; i++) {
        int lrow = (i < 4) ? (ty * 4 + i) : (64 + ty * 4 + i - 4);
        float inv = 1.0f / (nrm[i] + 1e-8f);
        size_t ob = (size_t)(b * LL + l0 + lrow) * DD + h * HD;
#pragma unroll
        for (int jj = 0; jj < 2; jj++) {
            int m = (jj == 0) ? tx * 4 : 64 + tx * 4;
            __nv_bfloat16 h0, l0v, h1, l1, h2, l2, h3, l3;
            split_bf16(acc[i][jj * 4 + 0] * inv, h0, l0v);
            split_bf16(acc[i][jj * 4 + 1] * inv, h1, l1);
            split_bf16(acc[i][jj * 4 + 2] * inv, h2, l2);
            split_bf16(acc[i][jj * 4 + 3] * inv, h3, l3);
            __nv_bfloat162 p0, p1, q0, q1;
            p0.x = h0; p0.y = h1; p1.x = h2; p1.y = h3;
            q0.x = l0v; q0.y = l1; q1.x = l2; q1.y = l3;
            *(__nv_bfloat162*)(ohi + ob + m) = p0; *(__nv_bfloat162*)(ohi + ob + m + 2) = p1;
            *(__nv_bfloat162*)(olo + ob + m) = q0; *(__nv_bfloat162*)(olo + ob + m + 2) = q1;
        }
    }
}

// ==================== rmsnorm ================================================
template<int EMIT_HL>
__global__ __launch_bounds__(256)
void rmsnorm_k(const float* __restrict__ a, const float* __restrict__ b,
               const float* __restrict__ g, float* __restrict__ out,
               __nv_bfloat16* __restrict__ ohi, __nv_bfloat16* __restrict__ olo)
{
    const int row = blockIdx.x;
    const int t = threadIdx.x;
    float4 av = ((const float4*)(a + (size_t)row * DD))[t];
    float4 bv = ((const float4*)(b + (size_t)row * DD))[t];
    float4 v = make_float4(av.x + bv.x, av.y + bv.y, av.z + bv.z, av.w + bv.w);
    float ss = v.x * v.x + v.y * v.y + v.z * v.z + v.w * v.w;
#pragma unroll
    for (int o = 16; o; o >>= 1) ss += __shfl_xor_sync(0xFFFFFFFFu, ss, o);
    __shared__ float ws[8];
    if ((t & 31) == 0) ws[t >> 5] = ss;
    __syncthreads();
    float tot = 0.0f;
#pragma unroll
    for (int w = 0; w < 8; w++) tot += ws[w];
    float sc = rsqrtf(tot * (1.0f / DD) + 1.1920929e-07f);
    float4 gv = ((const float4*)g)[t];
    float4 o4 = make_float4(v.x * sc * gv.x, v.y * sc * gv.y, v.z * sc * gv.z, v.w * sc * gv.w);
    ((float4*)(out + (size_t)row * DD))[t] = o4;
    if (EMIT_HL) {
        __nv_bfloat16 h0, l0, h1, l1, h2, l2, h3, l3;
        split_bf16(o4.x, h0, l0); split_bf16(o4.y, h1, l1);
        split_bf16(o4.z, h2, l2); split_bf16(o4.w, h3, l3);
        __nv_bfloat162 p0, p1, q0, q1;
        p0.x = h0; p0.y = h1; p1.x = h2; p1.y = h3;
        q0.x = l0; q0.y = l1; q1.x = l2; q1.y = l3;
        size_t ob = (size_t)row * DD + t * 4;
        *(__nv_bfloat162*)(ohi + ob) = p0; *(__nv_bfloat162*)(ohi + ob + 2) = p1;
        *(__nv_bfloat162*)(olo + ob) = q0; *(__nv_bfloat162*)(olo + ob + 2) = q1;
    }
}

// ============================== launcher =====================================
extern "C" void kernel_launch(void* const* d_in, const int* in_sizes, int n_in,
                              void* d_out, int out_size)
{
    const float* x     = (const float*)d_in[0];
    const float* W_qkv = (const float*)d_in[1];
    const float* W_out = (const float*)d_in[2];
    const float* g1    = (const float*)d_in[3];
    const float* W_ff1 = (const float*)d_in[4];
    const float* W_ff2 = (const float*)d_in[5];
    const float* g2    = (const float*)d_in[6];
    float* out = (float*)d_out;

    __nv_bfloat16 *big, *hl, *y1h, *y1l, *wt;
    float *t1, *y1, *kvb, *ksb, *kvp, *ksp;
    cudaGetSymbolAddress((void**)&big, g_big);
    cudaGetSymbolAddress((void**)&hl,  g_hl);
    cudaGetSymbolAddress((void**)&t1,  g_t1);
    cudaGetSymbolAddress((void**)&y1,  g_y1);
    cudaGetSymbolAddress((void**)&y1h, g_y1h);
    cudaGetSymbolAddress((void**)&y1l, g_y1l);
    cudaGetSymbolAddress((void**)&wt,  g_wt);
    cudaGetSymbolAddress((void**)&kvb, g_kv);
    cudaGetSymbolAddress((void**)&ksb, g_ks);
    cudaGetSymbolAddress((void**)&kvp, g_kvp);
    cudaGetSymbolAddress((void**)&ksp, g_ksp);

    cudaFuncSetAttribute(tcgemm_k<0>, cudaFuncAttributeMaxDynamicSharedMemorySize, GEMM_SMEM);
    cudaFuncSetAttribute(tcgemm_k<1>, cudaFuncAttributeMaxDynamicSharedMemorySize, GEMM_SMEM);

    __nv_bfloat16* xhi = hl;
    __nv_bfloat16* xlo = hl + (size_t)MM * DD;
    __nv_bfloat16* athi = hl;                       // alias: x hl dead after GEMM1
    __nv_bfloat16* atlo = hl + (size_t)MM * DD;
    float* qkvf = (float*)big;                      // 192MB of 268MB arena
    __nv_bfloat16* ffhi = big;                      // alias: qkv dead after attn_out
    __nv_bfloat16* fflo = big + (size_t)MM * DFF;
    __nv_bfloat16* whi = wt;
    __nv_bfloat16* wlo = wt + (size_t)DFF * DD;
    float* t2 = t1;                                 // t1 dead after rmsnorm1

    // 1) x -> hi/lo
    cvt_hl_k<<<MM * DD / 1024, 256>>>(x, xhi, xlo, MM * DD);
    // 2) W_qkv^T hi/lo ; qkv = x @ W_qkv  (fp32 out)
    wtr_k<<<dim3(3 * DD / 32, DD / 32), dim3(32, 8)>>>(W_qkv, whi, wlo, DD, 3 * DD);
    tcgemm_k<0><<<dim3(3 * DD / TN, MM / TM), 256, GEMM_SMEM>>>(
        xhi, xlo, whi, wlo, qkvf, nullptr, nullptr, MM, 3 * DD, DD);
    // 3) linear attention (fp32) -> attn hi/lo
    attn_kv_k<<<dim3(BB * HH, NSPLIT), 256>>>(qkvf, kvp, ksp);
    {
        int tot = BB * HH * HD * HD + BB * HH * HD;
        kv_reduce_k<<<(tot + 255) / 256, 256>>>(kvp, ksp, kvb, ksb);
    }
    attn_out_k<<<dim3(BB * HH, LL / 128), 256>>>(qkvf, kvb, ksb, athi, atlo);
    // 4) t1 = attn @ W_out
    wtr_k<<<dim3(DD / 32, DD / 32), dim3(32, 8)>>>(W_out, whi, wlo, DD, DD);
    tcgemm_k<0><<<dim3(DD / TN, MM / TM), 256, GEMM_SMEM>>>(
        athi, atlo, whi, wlo, t1, nullptr, nullptr, MM, DD, DD);
    // 5) y1 = rmsnorm(t1 + x) (+ hi/lo)
    rmsnorm_k<1><<<MM, 256>>>(t1, x, g1, y1, y1h, y1l);
    // 6) ff = gelu(y1 @ W_ff1) -> hi/lo directly
    wtr_k<<<dim3(DFF / 32, DD / 32), dim3(32, 8)>>>(W_ff1, whi, wlo, DD, DFF);
    tcgemm_k<1><<<dim3(DFF / TN, MM / TM), 256, GEMM_SMEM>>>(
        y1h, y1l, whi, wlo, nullptr, ffhi, fflo, MM, DFF, DD);
    // 7) t2 = ff @ W_ff2
    wtr_k<<<dim3(DD / 32, DFF / 32), dim3(32, 8)>>>(W_ff2, whi, wlo, DFF, DD);
    tcgemm_k<0><<<dim3(DD / TN, MM / TM), 256, GEMM_SMEM>>>(
        ffhi, fflo, whi, wlo, t2, nullptr, nullptr, MM, DD, DFF);
    // 8) out = rmsnorm(t2 + y1)
    rmsnorm_k<0><<<MM, 256>>>(t2, y1, g2, out, nullptr, nullptr);
}